// round 3
// baseline (speedup 1.0000x reference)
#include <cuda_runtime.h>

#define B_TOT 4096
#define T_ENC 168
#define T_DEC 24
#define NF    32
#define NT    8
#define HID   64
#define NG    256   // 4*HID

// Phase-1 scratch: XG0[b][t][g] = x[b,t,:] @ Wih0^T + bih0 + bhh0  (704 MB)
__device__ float g_xg0[(size_t)B_TOT * T_ENC * NG];

typedef unsigned long long u64;

// ---------------------------------------------------------------------------
// packed fp32 + fast activation helpers
// ---------------------------------------------------------------------------
__device__ __forceinline__ u64 pack2(float v) {
    u64 r;
    unsigned int b = __float_as_uint(v);
    asm("mov.b64 %0, {%1, %2};" : "=l"(r) : "r"(b), "r"(b));
    return r;
}
__device__ __forceinline__ void fma2(u64& acc, u64 a, u64 b) {
    asm("fma.rn.f32x2 %0, %1, %2, %0;" : "+l"(acc) : "l"(a), "l"(b));
}
__device__ __forceinline__ void add2(u64& acc, u64 a) {
    asm("add.rn.f32x2 %0, %0, %1;" : "+l"(acc) : "l"(a));
}
__device__ __forceinline__ float2 unpack2(u64 v) {
    unsigned int lo, hi;
    asm("mov.b64 {%0, %1}, %2;" : "=r"(lo), "=r"(hi) : "l"(v));
    return make_float2(__uint_as_float(lo), __uint_as_float(hi));
}
__device__ __forceinline__ float ftanh(float x) {      // MUFU.TANH
    float y;
    asm("tanh.approx.f32 %0, %1;" : "=f"(y) : "f"(x));
    return y;
}
__device__ __forceinline__ float fsig(float x) {       // 1 MUFU + 1 FMA
    return fmaf(ftanh(0.5f * x), 0.5f, 0.5f);
}

// ---------------------------------------------------------------------------
// GEMM tile, interleaved weights.
//   hT : transposed activations [K][hstride], rows r0..r0+3 via LDS.128
//   wI : u64 array, layout [k][j2(0..31)][blk(0..3)] -> 128 u64 per k
//   lane tile: 4 rows x (2 cols = 1 u64) x 4 blks = 16 u64 accs
//   per k: 1 LDS.128 (hT) + 2 LDS.128 (w) + 4 pack2 + 16 FMA2
// ---------------------------------------------------------------------------
__device__ __forceinline__ void gemm2i(
    u64 acc[4][4], const float* __restrict__ hT, int hstride,
    const u64* __restrict__ wI, int K, int r0, int j2)
{
#pragma unroll 4
    for (int k = 0; k < K; k++) {
        float4 a = *(const float4*)&hT[k * hstride + r0];
        const u64* wr = wI + (k * 32 + j2) * 4;
        ulonglong2 wA = *(const ulonglong2*)(wr);       // blk0, blk1
        ulonglong2 wB = *(const ulonglong2*)(wr + 2);   // blk2, blk3
        u64 h0 = pack2(a.x), h1 = pack2(a.y), h2 = pack2(a.z), h3 = pack2(a.w);
        fma2(acc[0][0], h0, wA.x); fma2(acc[0][1], h0, wA.y);
        fma2(acc[0][2], h0, wB.x); fma2(acc[0][3], h0, wB.y);
        fma2(acc[1][0], h1, wA.x); fma2(acc[1][1], h1, wA.y);
        fma2(acc[1][2], h1, wB.x); fma2(acc[1][3], h1, wB.y);
        fma2(acc[2][0], h2, wA.x); fma2(acc[2][1], h2, wA.y);
        fma2(acc[2][2], h2, wB.x); fma2(acc[2][3], h2, wB.y);
        fma2(acc[3][0], h3, wA.x); fma2(acc[3][1], h3, wA.y);
        fma2(acc[3][2], h3, wB.x); fma2(acc[3][3], h3, wB.y);
    }
}

// PyTorch gate order: blk0=i, blk1=f, blk2=g, blk3=o
__device__ __forceinline__ void cell_update(
    const u64 acc[4][4], float c[4][2], float hn[4][2])
{
#pragma unroll
    for (int rr = 0; rr < 4; rr++) {
        float2 gi = unpack2(acc[rr][0]);
        float2 gf = unpack2(acc[rr][1]);
        float2 gg = unpack2(acc[rr][2]);
        float2 go = unpack2(acc[rr][3]);
        float cn0 = fmaf(fsig(gf.x), c[rr][0], fsig(gi.x) * ftanh(gg.x));
        float cn1 = fmaf(fsig(gf.y), c[rr][1], fsig(gi.y) * ftanh(gg.y));
        c[rr][0] = cn0; c[rr][1] = cn1;
        hn[rr][0] = fsig(go.x) * ftanh(cn0);
        hn[rr][1] = fsig(go.y) * ftanh(cn1);
    }
}

// store hn (4 rows x 2 j) into transposed hT[j][row] (stride 32)
__device__ __forceinline__ void h_store(
    const float hn[4][2], float* __restrict__ hT, int r0, int jcol)
{
    *(float4*)&hT[(jcol + 0) * 32 + r0] =
        make_float4(hn[0][0], hn[1][0], hn[2][0], hn[3][0]);
    *(float4*)&hT[(jcol + 1) * 32 + r0] =
        make_float4(hn[0][1], hn[1][1], hn[2][1], hn[3][1]);
}

// interleaved-weight scatter index for source gate g, row k (float index)
__device__ __forceinline__ int widx(int k, int g) {
    int e = g & 1, j2 = (g >> 1) & 31, b = g >> 6;
    return ((k * 32 + j2) * 4 + b) * 2 + e;
}

// ---------------------------------------------------------------------------
// Phase 1: XG0 precompute. Block = 64 (b,t) pairs, 512 threads.
// ---------------------------------------------------------------------------
#define XS_STRIDE 72
__global__ void __launch_bounds__(512) xg0_kernel(
    const float* __restrict__ x, const float* __restrict__ Wih0,
    const float* __restrict__ bih0, const float* __restrict__ bhh0)
{
    __shared__ float xs[NF * XS_STRIDE];       // transposed [k][row], 64 rows
    __shared__ u64 wI[NF * 128];               // interleaved, 32 KB
    __shared__ float bs[NG];

    const int tid = threadIdx.x;
    const int p0 = blockIdx.x * 64;
    float* wf = (float*)wI;

    for (int idx = tid; idx < NG * NF; idx += 512) {
        int k = idx & 31, g = idx >> 5;                  // Wih0[g][k]
        wf[widx(k, g)] = Wih0[idx];
    }
    for (int idx = tid; idx < 64 * NF; idx += 512) {
        int r = idx >> 5, k = idx & 31;                  // coalesced x read
        xs[k * XS_STRIDE + r] = x[(size_t)(p0 + r) * NF + k];
    }
    if (tid < NG) bs[tid] = bih0[tid] + bhh0[tid];
    __syncthreads();

    const int wid = tid >> 5, lane = tid & 31;
    const int rh = wid >> 3, w8 = wid & 7;
    const int r0 = rh * 32 + (lane >> 2) * 4;
    const int j2 = w8 * 4 + (lane & 3);
    const int jcol = j2 * 2;

    u64 acc[4][4];
#pragma unroll
    for (int blk = 0; blk < 4; blk++) {
        u64 b = *(const u64*)&bs[blk * 64 + jcol];
#pragma unroll
        for (int rr = 0; rr < 4; rr++) acc[rr][blk] = b;
    }

    gemm2i(acc, xs, XS_STRIDE, wI, NF, r0 - rh * 32 + rh * 32, j2);
    // note: hT index uses absolute row r0 within 64-row buffer:
    // gemm2i computed with hT stride XS_STRIDE and r0 spanning 0..63 — OK.

#pragma unroll
    for (int rr = 0; rr < 4; rr++) {
        float* dst = g_xg0 + (size_t)(p0 + r0 + rr) * NG + jcol;
#pragma unroll
        for (int blk = 0; blk < 4; blk++)
            *(u64*)(dst + blk * 64) = acc[rr][blk];
    }
}

// ---------------------------------------------------------------------------
// Phase 2 smem layout (floats). dinT | h0T | h1T contiguous, stride 32.
// Weights stored interleaved as u64[k][32][4].
// ---------------------------------------------------------------------------
#define SM_W0    0                         // 72 rows * 256 = 18432 fl
#define SM_W1    (SM_W0 + 72 * NG)         // 128 rows * 256 = 32768 fl
#define SM_B0    (SM_W1 + 128 * NG)
#define SM_B1    (SM_B0 + NG)
#define SM_FCW   (SM_B1 + NG)              // 512
#define SM_FCB   (SM_FCW + HID * NT)       // 16
#define SM_DIN   (SM_FCB + 16)             // 8*32
#define SM_H0    (SM_DIN + NT * 32)        // 64*32
#define SM_H1    (SM_H0 + HID * 32)        // 64*32
#define SM_TOTAL (SM_H1 + HID * 32)        // 56592 fl = 226368 B
#define SMEM_BYTES (SM_TOTAL * 4)

__global__ void __launch_bounds__(256, 1) seq2seq_kernel(
    const float* __restrict__ eWhh0,
    const float* __restrict__ eWih1, const float* __restrict__ eWhh1,
    const float* __restrict__ ebih1, const float* __restrict__ ebhh1,
    const float* __restrict__ dWih0, const float* __restrict__ dWhh0,
    const float* __restrict__ dbih0, const float* __restrict__ dbhh0,
    const float* __restrict__ dWih1, const float* __restrict__ dWhh1,
    const float* __restrict__ dbih1, const float* __restrict__ dbhh1,
    const float* __restrict__ fcW, const float* __restrict__ fcBias,
    float* __restrict__ out)
{
    extern __shared__ float sm[];
    float* w0f = sm + SM_W0;
    float* w1f = sm + SM_W1;
    const u64* w0I = (const u64*)w0f;
    const u64* w1I = (const u64*)w1f;
    float* b0s = sm + SM_B0;
    float* b1s = sm + SM_B1;
    float* fcw = sm + SM_FCW;
    float* fcb = sm + SM_FCB;
    float* dinT = sm + SM_DIN;
    float* h0T = sm + SM_H0;
    float* h1T = sm + SM_H1;

    const int tid = threadIdx.x;
    const int b0 = blockIdx.x * 32;
    const int wid = tid >> 5, lane = tid & 31;
    const int r0 = (lane >> 2) * 4;
    const int j2 = wid * 4 + (lane & 3);
    const int jcol = j2 * 2;

    // ---- load encoder weights, interleaved ----
    for (int idx = tid; idx < HID * NG; idx += 256) {
        int k = idx >> 8, g = idx & 255;
        float v0 = eWhh0[g * HID + k];
        float v1 = eWih1[g * HID + k];
        float v2 = eWhh1[g * HID + k];
        w0f[widx(k, g)] = v0;
        w1f[widx(k, g)] = v1;
        w1f[widx(k + HID, g)] = v2;
    }
    if (tid < NG) b1s[tid] = ebih1[tid] + ebhh1[tid];
    for (int idx = tid; idx < HID * 32; idx += 256) { h0T[idx] = 0.f; h1T[idx] = 0.f; }
    __syncthreads();

    float c0[4][2] = {{0,0},{0,0},{0,0},{0,0}};
    float c1[4][2] = {{0,0},{0,0},{0,0},{0,0}};
    u64 acc[4][4];
    u64 xg[4][4];
    float hn[4][2];

    // ================= encoder =================
    for (int t = 0; t < T_ENC; t++) {
        // ---- layer 0: prefetch XG0 into regs, GEMM from zero, add at end ----
#pragma unroll
        for (int rr = 0; rr < 4; rr++) {
            const float* src =
                g_xg0 + ((size_t)(b0 + r0 + rr) * T_ENC + t) * NG + jcol;
#pragma unroll
            for (int blk = 0; blk < 4; blk++)
                xg[rr][blk] = *(const u64*)(src + blk * 64);
        }
#pragma unroll
        for (int rr = 0; rr < 4; rr++)
#pragma unroll
            for (int blk = 0; blk < 4; blk++) acc[rr][blk] = 0ull;

        gemm2i(acc, h0T, 32, w0I, HID, r0, j2);
#pragma unroll
        for (int rr = 0; rr < 4; rr++)
#pragma unroll
            for (int blk = 0; blk < 4; blk++) add2(acc[rr][blk], xg[rr][blk]);
        cell_update(acc, c0, hn);
        __syncthreads();                 // A: all warps done reading old h0
        h_store(hn, h0T, r0, jcol);
        __syncthreads();                 // B: new h0 visible

        // ---- layer 1: [h0;h1] contiguous, K=128 ----
#pragma unroll
        for (int blk = 0; blk < 4; blk++) {
            u64 b = *(const u64*)&b1s[blk * 64 + jcol];
#pragma unroll
            for (int rr = 0; rr < 4; rr++) acc[rr][blk] = b;
        }
        gemm2i(acc, h0T, 32, w1I, 2 * HID, r0, j2);
        cell_update(acc, c1, hn);
        __syncthreads();                 // C: all warps done reading old h1
        h_store(hn, h1T, r0, jcol);
        // no sync needed here: next readers of h1T are after next A+B barriers
    }
    __syncthreads();                     // weights about to be overwritten

    // ---- swap in decoder weights ----
    for (int idx = tid; idx < NT * NG; idx += 256) {     // dec_Wih0 -> rows 0..7
        int k = idx >> 8, g = idx & 255;
        w0f[widx(k, g)] = dWih0[g * NT + k];
    }
    for (int idx = tid; idx < HID * NG; idx += 256) {
        int k = idx >> 8, g = idx & 255;
        w0f[widx(k + NT, g)] = dWhh0[g * HID + k];        // rows 8..71
        w1f[widx(k, g)] = dWih1[g * HID + k];
        w1f[widx(k + HID, g)] = dWhh1[g * HID + k];
    }
    if (tid < NG) {
        b0s[tid] = dbih0[tid] + dbhh0[tid];
        b1s[tid] = dbih1[tid] + dbhh1[tid];
    }
    for (int idx = tid; idx < HID * NT; idx += 256) {     // fc_W[o][j] -> fcw[j][o]
        int j = idx >> 3, o = idx & 7;
        fcw[idx] = fcW[o * HID + j];
    }
    if (tid < NT) fcb[tid] = fcBias[tid];
    for (int idx = tid; idx < NT * 32; idx += 256) dinT[idx] = 0.f;
    __syncthreads();

    // ================= decoder =================
    for (int s = 0; s < T_DEC; s++) {
        // layer 0: [din(8); h0(64)] contiguous, K=72
#pragma unroll
        for (int blk = 0; blk < 4; blk++) {
            u64 b = *(const u64*)&b0s[blk * 64 + jcol];
#pragma unroll
            for (int rr = 0; rr < 4; rr++) acc[rr][blk] = b;
        }
        gemm2i(acc, dinT, 32, w0I, NT + HID, r0, j2);
        cell_update(acc, c0, hn);
        __syncthreads();
        h_store(hn, h0T, r0, jcol);
        __syncthreads();

        // layer 1: [h0;h1] contiguous, K=128
#pragma unroll
        for (int blk = 0; blk < 4; blk++) {
            u64 b = *(const u64*)&b1s[blk * 64 + jcol];
#pragma unroll
            for (int rr = 0; rr < 4; rr++) acc[rr][blk] = b;
        }
        gemm2i(acc, h0T, 32, w1I, 2 * HID, r0, j2);
        cell_update(acc, c1, hn);
        __syncthreads();
        h_store(hn, h1T, r0, jcol);
        __syncthreads();                 // h1 visible to FC

        // FC: one (row, out) per thread; h1T is transposed [j][row]
        {
            int r = tid >> 3, o = tid & 7;
            float a = fcb[o];
#pragma unroll 8
            for (int j = 0; j < HID; j++)
                a = fmaf(h1T[j * 32 + r], fcw[j * NT + o], a);
            out[((size_t)(b0 + r) * T_DEC + s) * NT + o] = a;
            dinT[o * 32 + r] = a;
        }
        __syncthreads();                 // dinT visible to next layer 0
    }
}

// ---------------------------------------------------------------------------
extern "C" void kernel_launch(void* const* d_in, const int* in_sizes, int n_in,
                              void* d_out, int out_size)
{
    const float* x     = (const float*)d_in[0];
    const float* eWih0 = (const float*)d_in[1];
    const float* eWhh0 = (const float*)d_in[2];
    const float* ebih0 = (const float*)d_in[3];
    const float* ebhh0 = (const float*)d_in[4];
    const float* eWih1 = (const float*)d_in[5];
    const float* eWhh1 = (const float*)d_in[6];
    const float* ebih1 = (const float*)d_in[7];
    const float* ebhh1 = (const float*)d_in[8];
    const float* dWih0 = (const float*)d_in[9];
    const float* dWhh0 = (const float*)d_in[10];
    const float* dbih0 = (const float*)d_in[11];
    const float* dbhh0 = (const float*)d_in[12];
    const float* dWih1 = (const float*)d_in[13];
    const float* dWhh1 = (const float*)d_in[14];
    const float* dbih1 = (const float*)d_in[15];
    const float* dbhh1 = (const float*)d_in[16];
    const float* fcW   = (const float*)d_in[17];
    const float* fcb   = (const float*)d_in[18];
    float* out = (float*)d_out;

    cudaFuncSetAttribute(seq2seq_kernel,
                         cudaFuncAttributeMaxDynamicSharedMemorySize, SMEM_BYTES);

    xg0_kernel<<<(B_TOT * T_ENC) / 64, 512>>>(x, eWih0, ebih0, ebhh0);
    seq2seq_kernel<<<B_TOT / 32, 256, SMEM_BYTES>>>(
        eWhh0, eWih1, eWhh1, ebih1, ebhh1,
        dWih0, dWhh0, dbih0, dbhh0, dWih1, dWhh1, dbih1, dbhh1,
        fcW, fcb, out);
}

// round 5
// speedup vs baseline: 1.1270x; 1.1270x over previous
#include <cuda_runtime.h>

#define B_TOT 4096
#define T_ENC 168
#define T_DEC 24
#define NF    32
#define NT    8
#define HID   64
#define NG    256   // 4*HID

// Phase-1 scratch: XG0[b][t][g] = x[b,t,:] @ Wih0^T + bih0 + bhh0  (704 MB)
__device__ float g_xg0[(size_t)B_TOT * T_ENC * NG];

typedef unsigned long long u64;

// ---------------------------------------------------------------------------
// packed fp32 + fast activation helpers
// ---------------------------------------------------------------------------
__device__ __forceinline__ u64 pack2(float v) {
    u64 r;
    unsigned int b = __float_as_uint(v);
    asm("mov.b64 %0, {%1, %2};" : "=l"(r) : "r"(b), "r"(b));
    return r;
}
__device__ __forceinline__ void fma2(u64& acc, u64 a, u64 b) {
    asm("fma.rn.f32x2 %0, %1, %2, %0;" : "+l"(acc) : "l"(a), "l"(b));
}
__device__ __forceinline__ void add2(u64& acc, u64 a) {
    asm("add.rn.f32x2 %0, %0, %1;" : "+l"(acc) : "l"(a));
}
__device__ __forceinline__ float2 unpack2(u64 v) {
    unsigned int lo, hi;
    asm("mov.b64 {%0, %1}, %2;" : "=r"(lo), "=r"(hi) : "l"(v));
    return make_float2(__uint_as_float(lo), __uint_as_float(hi));
}
__device__ __forceinline__ float ftanh(float x) {      // MUFU.TANH
    float y;
    asm("tanh.approx.f32 %0, %1;" : "=f"(y) : "f"(x));
    return y;
}
__device__ __forceinline__ float fsig(float x) {       // 1 MUFU + 1 FMA
    return fmaf(ftanh(0.5f * x), 0.5f, 0.5f);
}

// interleaved-weight scatter index for source gate g, row k (float index)
// layout: u64[k][j2(0..31)][blk(0..3)]
__device__ __forceinline__ int widx(int k, int g) {
    int e = g & 1, j2 = (g >> 1) & 31, b = g >> 6;
    return ((k * 32 + j2) * 4 + b) * 2 + e;
}

// ---------------------------------------------------------------------------
// Phase-1 GEMM (R2-proven): 4 rows x 8 cols per thread, plain k-major weights
// ---------------------------------------------------------------------------
__device__ __forceinline__ void gemm2(
    u64 acc[4][4], const float* __restrict__ hT, int hstride,
    const float* __restrict__ ws, int wstride, int K, int r0, int jcol)
{
#pragma unroll 2
    for (int k = 0; k < K; k += 4) {
#pragma unroll
        for (int kk = 0; kk < 4; kk++) {
            float4 a = *(const float4*)&hT[(k + kk) * hstride + r0];
            const float* wr = ws + (k + kk) * wstride + jcol;
            u64 w0 = *(const u64*)(wr);
            u64 w1 = *(const u64*)(wr + 64);
            u64 w2 = *(const u64*)(wr + 128);
            u64 w3 = *(const u64*)(wr + 192);
            u64 h0 = pack2(a.x), h1 = pack2(a.y), h2 = pack2(a.z), h3 = pack2(a.w);
            fma2(acc[0][0], h0, w0); fma2(acc[0][1], h0, w1);
            fma2(acc[0][2], h0, w2); fma2(acc[0][3], h0, w3);
            fma2(acc[1][0], h1, w0); fma2(acc[1][1], h1, w1);
            fma2(acc[1][2], h1, w2); fma2(acc[1][3], h1, w3);
            fma2(acc[2][0], h2, w0); fma2(acc[2][1], h2, w1);
            fma2(acc[2][2], h2, w2); fma2(acc[2][3], h2, w3);
            fma2(acc[3][0], h3, w0); fma2(acc[3][1], h3, w1);
            fma2(acc[3][2], h3, w2); fma2(acc[3][3], h3, w3);
        }
    }
}

// ---------------------------------------------------------------------------
// Phase-2 GEMM (R3-proven mapping): 4 rows x 8 cols, interleaved weights.
//   per k: 1 LDS.128 (hT) + 2 LDS.128 (w) + 4 pack + 16 FMA2
// ---------------------------------------------------------------------------
__device__ __forceinline__ void gemm2i(
    u64 acc[4][4], const float* __restrict__ hT,
    const u64* __restrict__ wI, int K, int r0, int j2)
{
#pragma unroll 4
    for (int k = 0; k < K; k++) {
        float4 a = *(const float4*)&hT[k * 32 + r0];
        const u64* wr = wI + (k * 32 + j2) * 4;
        ulonglong2 wA = *(const ulonglong2*)(wr);       // blk0, blk1
        ulonglong2 wB = *(const ulonglong2*)(wr + 2);   // blk2, blk3
        u64 h0 = pack2(a.x), h1 = pack2(a.y), h2 = pack2(a.z), h3 = pack2(a.w);
        fma2(acc[0][0], h0, wA.x); fma2(acc[0][1], h0, wA.y);
        fma2(acc[0][2], h0, wB.x); fma2(acc[0][3], h0, wB.y);
        fma2(acc[1][0], h1, wA.x); fma2(acc[1][1], h1, wA.y);
        fma2(acc[1][2], h1, wB.x); fma2(acc[1][3], h1, wB.y);
        fma2(acc[2][0], h2, wA.x); fma2(acc[2][1], h2, wA.y);
        fma2(acc[2][2], h2, wB.x); fma2(acc[2][3], h2, wB.y);
        fma2(acc[3][0], h3, wA.x); fma2(acc[3][1], h3, wA.y);
        fma2(acc[3][2], h3, wB.x); fma2(acc[3][3], h3, wB.y);
    }
}

// PyTorch gate order: blk0=i, blk1=f, blk2=g, blk3=o
__device__ __forceinline__ void cell_update(
    const u64 acc[4][4], float c[4][2], float hn[4][2])
{
#pragma unroll
    for (int rr = 0; rr < 4; rr++) {
        float2 gi = unpack2(acc[rr][0]);
        float2 gf = unpack2(acc[rr][1]);
        float2 gg = unpack2(acc[rr][2]);
        float2 go = unpack2(acc[rr][3]);
        float cn0 = fmaf(fsig(gf.x), c[rr][0], fsig(gi.x) * ftanh(gg.x));
        float cn1 = fmaf(fsig(gf.y), c[rr][1], fsig(gi.y) * ftanh(gg.y));
        c[rr][0] = cn0; c[rr][1] = cn1;
        hn[rr][0] = fsig(go.x) * ftanh(cn0);
        hn[rr][1] = fsig(go.y) * ftanh(cn1);
    }
}

// store hn (4 rows x 2 j) into transposed hT[j][row] (stride 32)
__device__ __forceinline__ void h_store(
    const float hn[4][2], float* __restrict__ hT, int r0, int jcol)
{
    *(float4*)&hT[(jcol + 0) * 32 + r0] =
        make_float4(hn[0][0], hn[1][0], hn[2][0], hn[3][0]);
    *(float4*)&hT[(jcol + 1) * 32 + r0] =
        make_float4(hn[0][1], hn[1][1], hn[2][1], hn[3][1]);
}

// ---------------------------------------------------------------------------
// Phase 1: XG0 precompute (R2-proven). Block = 32 (b,t) pairs, 256 threads.
// ---------------------------------------------------------------------------
#define XS_STRIDE 36
__global__ void __launch_bounds__(256) xg0_kernel(
    const float* __restrict__ x, const float* __restrict__ Wih0,
    const float* __restrict__ bih0, const float* __restrict__ bhh0)
{
    __shared__ float xs[NF * XS_STRIDE];   // transposed [k][row]
    __shared__ float ws[NF * 258];         // k-major padded
    __shared__ float bs[NG];

    const int tid = threadIdx.x;
    const int p0 = blockIdx.x * 32;

    for (int idx = tid; idx < NG * NF; idx += 256) {    // coalesced LDG
        int k = idx & 31, g = idx >> 5;                  // Wih0[g][k]
        ws[k * 258 + g] = Wih0[idx];
    }
    for (int idx = tid; idx < 32 * NF; idx += 256) {
        int r = idx >> 5, k = idx & 31;
        xs[k * XS_STRIDE + r] = x[(size_t)(p0 + r) * NF + k];
    }
    if (tid < NG) bs[tid] = bih0[tid] + bhh0[tid];
    __syncthreads();

    const int wid = tid >> 5, lane = tid & 31;
    const int r0 = (lane >> 2) * 4;
    const int jcol = wid * 8 + (lane & 3) * 2;

    u64 acc[4][4];
#pragma unroll
    for (int blk = 0; blk < 4; blk++) {
        u64 b = *(const u64*)&bs[blk * 64 + jcol];
#pragma unroll
        for (int rr = 0; rr < 4; rr++) acc[rr][blk] = b;
    }

    gemm2(acc, xs, XS_STRIDE, ws, 258, NF, r0, jcol);

#pragma unroll
    for (int rr = 0; rr < 4; rr++) {
        float* dst = g_xg0 + (size_t)(p0 + r0 + rr) * NG + jcol;
#pragma unroll
        for (int blk = 0; blk < 4; blk++)
            *(u64*)(dst + blk * 64) = acc[rr][blk];
    }
}

// ---------------------------------------------------------------------------
// Phase 2 smem layout (floats). dinT | h0T | h1T contiguous, stride 32.
// Weights stored interleaved as u64[k][32][4].
// Encoder uses w0 rows 0..63 only; rows 64..71 (8 KB, decoder-only) double as
// the second h0 buffer during the encoder.
// ---------------------------------------------------------------------------
#define SM_W0    0                         // 72 rows * 256
#define SM_H0B   (SM_W0 + 64 * NG)         // 2048 fl = encoder h0 buffer B
#define SM_W1    (SM_W0 + 72 * NG)         // 128 rows * 256
#define SM_B0    (SM_W1 + 128 * NG)
#define SM_B1    (SM_B0 + NG)
#define SM_FCW   (SM_B1 + NG)              // 512
#define SM_FCB   (SM_FCW + HID * NT)       // 16
#define SM_DIN   (SM_FCB + 16)             // 8*32
#define SM_H0    (SM_DIN + NT * 32)        // 64*32 (buffer A / decoder h0)
#define SM_H1    (SM_H0 + HID * 32)        // 64*32
#define SM_TOTAL (SM_H1 + HID * 32)        // 56592 fl = 226368 B
#define SMEM_BYTES (SM_TOTAL * 4)

__global__ void __launch_bounds__(256, 1) seq2seq_kernel(
    const float* __restrict__ eWhh0,
    const float* __restrict__ eWih1, const float* __restrict__ eWhh1,
    const float* __restrict__ ebih1, const float* __restrict__ ebhh1,
    const float* __restrict__ dWih0, const float* __restrict__ dWhh0,
    const float* __restrict__ dbih0, const float* __restrict__ dbhh0,
    const float* __restrict__ dWih1, const float* __restrict__ dWhh1,
    const float* __restrict__ dbih1, const float* __restrict__ dbhh1,
    const float* __restrict__ fcW, const float* __restrict__ fcBias,
    float* __restrict__ out)
{
    extern __shared__ float sm[];
    float* w0f = sm + SM_W0;
    float* w1f = sm + SM_W1;
    const u64* w0I = (const u64*)w0f;
    const u64* w1I = (const u64*)w1f;
    float* b0s = sm + SM_B0;
    float* b1s = sm + SM_B1;
    float* fcw = sm + SM_FCW;
    float* fcb = sm + SM_FCB;
    float* dinT = sm + SM_DIN;
    float* h0A = sm + SM_H0;               // h0 buffer A (also decoder h0)
    float* h0B = sm + SM_H0B;              // h0 buffer B (encoder only)
    float* h1T = sm + SM_H1;

    const int tid = threadIdx.x;
    const int b0 = blockIdx.x * 32;
    const int wid = tid >> 5, lane = tid & 31;
    const int r0 = (lane >> 2) * 4;
    const int j2 = wid * 4 + (lane & 3);
    const int jcol = j2 * 2;

    // ---- load encoder weights, interleaved (w0 rows 0..63 only) ----
    for (int idx = tid; idx < HID * NG; idx += 256) {
        int k = idx >> 8, g = idx & 255;
        w0f[widx(k, g)] = eWhh0[g * HID + k];
        w1f[widx(k, g)] = eWih1[g * HID + k];
        w1f[widx(k + HID, g)] = eWhh1[g * HID + k];
    }
    if (tid < NG) b1s[tid] = ebih1[tid] + ebhh1[tid];
    for (int idx = tid; idx < HID * 32; idx += 256) { h0A[idx] = 0.f; h1T[idx] = 0.f; }
    __syncthreads();

    float c0[4][2] = {{0,0},{0,0},{0,0},{0,0}};
    float c1[4][2] = {{0,0},{0,0},{0,0},{0,0}};
    u64 acc[4][4];
    u64 xg[4][4];
    float hn[4][2];

    // ================= encoder (2 barriers/step, h0 double-buffered) =======
    // h0(t) is stored into buf[(t&1)^1]; h0(t-1) is read from buf[t&1].
    // T_ENC=168 even -> final h0 lands in buffer A (= decoder's h0).
    for (int t = 0; t < T_ENC; t++) {
        float* h0rd = (t & 1) ? h0B : h0A;
        float* h0wr = (t & 1) ? h0A : h0B;

        // ---- layer 0: prefetch XG0 into regs, GEMM from zero, add at end ----
#pragma unroll
        for (int rr = 0; rr < 4; rr++) {
            const float* src =
                g_xg0 + ((size_t)(b0 + r0 + rr) * T_ENC + t) * NG + jcol;
#pragma unroll
            for (int blk = 0; blk < 4; blk++)
                xg[rr][blk] = *(const u64*)(src + blk * 64);
        }
#pragma unroll
        for (int rr = 0; rr < 4; rr++)
#pragma unroll
            for (int blk = 0; blk < 4; blk++) acc[rr][blk] = 0ull;

        gemm2i(acc, h0rd, w0I, HID, r0, j2);
#pragma unroll
        for (int rr = 0; rr < 4; rr++)
#pragma unroll
            for (int blk = 0; blk < 4; blk++) add2(acc[rr][blk], xg[rr][blk]);
        cell_update(acc, c0, hn);
        h_store(hn, h0wr, r0, jcol);       // WAR-safe: different buffer
        __syncthreads();                    // RAW: new h0 visible to all

        // ---- layer 1: h0(new) K=64, h1 K=64 ----
#pragma unroll
        for (int blk = 0; blk < 4; blk++) {
            u64 b = *(const u64*)&b1s[blk * 64 + jcol];
#pragma unroll
            for (int rr = 0; rr < 4; rr++) acc[rr][blk] = b;
        }
        gemm2i(acc, h0wr, w1I, HID, r0, j2);
        gemm2i(acc, h1T, w1I + HID * 32 * 4, HID, r0, j2);
        cell_update(acc, c1, hn);
        __syncthreads();                    // WAR: all done reading old h1
        h_store(hn, h1T, r0, jcol);
        // RAW for next step's h1 read is covered by next step's first barrier
    }
    __syncthreads();                        // h0B/w regions about to be reused

    // ---- swap in decoder weights ----
    for (int idx = tid; idx < NT * NG; idx += 256) {     // dec_Wih0 -> rows 0..7
        int k = idx >> 8, g = idx & 255;
        w0f[widx(k, g)] = dWih0[g * NT + k];
    }
    for (int idx = tid; idx < HID * NG; idx += 256) {
        int k = idx >> 8, g = idx & 255;
        w0f[widx(k + NT, g)] = dWhh0[g * HID + k];        // rows 8..71
        w1f[widx(k, g)] = dWih1[g * HID + k];
        w1f[widx(k + HID, g)] = dWhh1[g * HID + k];
    }
    if (tid < NG) {
        b0s[tid] = dbih0[tid] + dbhh0[tid];
        b1s[tid] = dbih1[tid] + dbhh1[tid];
    }
    for (int idx = tid; idx < HID * NT; idx += 256) {     // fc_W[o][j] -> fcw[j][o]
        int j = idx >> 3, o = idx & 7;
        fcw[idx] = fcW[o * HID + j];
    }
    if (tid < NT) fcb[tid] = fcBias[tid];
    for (int idx = tid; idx < NT * 32; idx += 256) dinT[idx] = 0.f;
    __syncthreads();

    // ================= decoder (R3-proven structure) =================
    for (int s = 0; s < T_DEC; s++) {
        // layer 0: [din(8); h0(64)] contiguous, K=72
#pragma unroll
        for (int blk = 0; blk < 4; blk++) {
            u64 b = *(const u64*)&b0s[blk * 64 + jcol];
#pragma unroll
            for (int rr = 0; rr < 4; rr++) acc[rr][blk] = b;
        }
        gemm2i(acc, dinT, w0I, NT + HID, r0, j2);
        cell_update(acc, c0, hn);
        __syncthreads();
        h_store(hn, h0A, r0, jcol);
        __syncthreads();

        // layer 1: [h0;h1] contiguous, K=128
#pragma unroll
        for (int blk = 0; blk < 4; blk++) {
            u64 b = *(const u64*)&b1s[blk * 64 + jcol];
#pragma unroll
            for (int rr = 0; rr < 4; rr++) acc[rr][blk] = b;
        }
        gemm2i(acc, h0A, w1I, 2 * HID, r0, j2);
        cell_update(acc, c1, hn);
        __syncthreads();
        h_store(hn, h1T, r0, jcol);
        __syncthreads();                 // h1 visible to FC

        // FC: one (row, out) per thread; h1T is transposed [j][row]
        {
            int r = tid >> 3, o = tid & 7;
            float a = fcb[o];
#pragma unroll 8
            for (int j = 0; j < HID; j++)
                a = fmaf(h1T[j * 32 + r], fcw[j * NT + o], a);
            out[((size_t)(b0 + r) * T_DEC + s) * NT + o] = a;
            dinT[o * 32 + r] = a;
        }
        __syncthreads();                 // dinT visible to next layer 0
    }
}

// ---------------------------------------------------------------------------
extern "C" void kernel_launch(void* const* d_in, const int* in_sizes, int n_in,
                              void* d_out, int out_size)
{
    const float* x     = (const float*)d_in[0];
    const float* eWih0 = (const float*)d_in[1];
    const float* eWhh0 = (const float*)d_in[2];
    const float* ebih0 = (const float*)d_in[3];
    const float* ebhh0 = (const float*)d_in[4];
    const float* eWih1 = (const float*)d_in[5];
    const float* eWhh1 = (const float*)d_in[6];
    const float* ebih1 = (const float*)d_in[7];
    const float* ebhh1 = (const float*)d_in[8];
    const float* dWih0 = (const float*)d_in[9];
    const float* dWhh0 = (const float*)d_in[10];
    const float* dbih0 = (const float*)d_in[11];
    const float* dbhh0 = (const float*)d_in[12];
    const float* dWih1 = (const float*)d_in[13];
    const float* dWhh1 = (const float*)d_in[14];
    const float* dbih1 = (const float*)d_in[15];
    const float* dbhh1 = (const float*)d_in[16];
    const float* fcW   = (const float*)d_in[17];
    const float* fcb   = (const float*)d_in[18];
    float* out = (float*)d_out;

    cudaFuncSetAttribute(seq2seq_kernel,
                         cudaFuncAttributeMaxDynamicSharedMemorySize, SMEM_BYTES);

    xg0_kernel<<<(B_TOT * T_ENC) / 32, 256>>>(x, eWih0, ebih0, ebhh0);
    seq2seq_kernel<<<B_TOT / 32, 256, SMEM_BYTES>>>(
        eWhh0, eWih1, eWhh1, ebih1, ebhh1,
        dWih0, dWhh0, dbih0, dbhh0, dWih1, dWhh1, dbih1, dbhh1,
        fcW, fcb, out);
}